// round 6
// baseline (speedup 1.0000x reference)
#include <cuda_runtime.h>
#include <cuda_bf16.h>
#include <cstdint>

#define Bn 64
#define Ln 256
#define Vn 256
#define En 256
#define Hn 1024
#define NG3 3072
#define NBLK 128           // persistent blocks; each owns 8 hidden units
#define NJb 8
#define HB (Hn*Bn)
#define SLAB 262144        // bytes per h slab: 2 ver * 64 ks * 4 mt * 16 rows * 32B
#define VERB 131072        // bytes per version within slab
#define BFRAG 24576        // u32 B-fragment words per block (hi+lo)
#define SM_B 98304         // B fragments in smem (bytes)
#define ABUFB 49152        // one A chunk buffer: 2 ver * 8 ks * 4 mt * 768B
#define SMEM_DYN (SM_B + 2*ABUFB)   // 196608 = 192KB

typedef unsigned int u32;
typedef unsigned long long u64;

__device__ float g_EW[Vn*NG3];                         // emb@Wi (+bh for r,z)
__device__ float g_HP[(size_t)(Ln+1)*HB];              // exact fp32 h, [t][b][j]
__device__ unsigned char g_YA[(size_t)(Ln+1)*SLAB];    // bf16 hi/lo tiled h slabs
__device__ u32 g_WF[(size_t)NBLK*BFRAG];               // B fragments per block
__device__ unsigned int g_ctr;

__device__ __forceinline__ u32 smem_u32(const void* p) {
    u32 a;
    asm("{ .reg .u64 t; cvta.to.shared.u64 t, %1; cvt.u32.u64 %0, t; }" : "=r"(a) : "l"(p));
    return a;
}
__device__ __forceinline__ void cp16(u32 dst, const void* src) {
    asm volatile("cp.async.cg.shared.global [%0], [%1], 16;" :: "r"(dst), "l"(src) : "memory");
}
__device__ __forceinline__ void cp_commit() {
    asm volatile("cp.async.commit_group;" ::: "memory");
}
template<int N> __device__ __forceinline__ void cp_wait() {
    asm volatile("cp.async.wait_group %0;" :: "n"(N) : "memory");
}
__device__ __forceinline__ void ldm4(u32 addr, u32& a0, u32& a1, u32& a2, u32& a3) {
    asm volatile("ldmatrix.sync.aligned.m8n8.x4.shared.b16 {%0,%1,%2,%3}, [%4];"
                 : "=r"(a0), "=r"(a1), "=r"(a2), "=r"(a3) : "r"(addr));
}
__device__ __forceinline__ void mma_bf16(float* c, const u32* a, u32 b0, u32 b1) {
    asm volatile("mma.sync.aligned.m16n8k16.row.col.f32.bf16.bf16.f32 "
        "{%0,%1,%2,%3}, {%4,%5,%6,%7}, {%8,%9}, {%0,%1,%2,%3};"
        : "+f"(c[0]), "+f"(c[1]), "+f"(c[2]), "+f"(c[3])
        : "r"(a[0]), "r"(a[1]), "r"(a[2]), "r"(a[3]), "r"(b0), "r"(b1));
}
__device__ __forceinline__ unsigned short bf16r(float x) {
    return __bfloat16_as_ushort(__float2bfloat16_rn(x));
}

// =================== reset ===================
__global__ void reset_kernel() {
    int tid = blockIdx.x * blockDim.x + threadIdx.x;
    int nt = gridDim.x * blockDim.x;
    for (int i = tid; i < HB; i += nt) g_HP[i] = 0.0f;
    for (int i = tid; i < SLAB / 4; i += nt) ((u32*)g_YA)[i] = 0u;
    if (tid == 0) g_ctr = 0u;
}

// =================== EW = embedding @ Wi (+ bh folded for r,z) ===================
__global__ __launch_bounds__(256) void ew_kernel(const float* __restrict__ emb,
                                                 const float* __restrict__ Wi,
                                                 const float* __restrict__ bh) {
    __shared__ float semb[32][En];
    int vbase = blockIdx.y * 32, cbase = blockIdx.x * 128, tid = threadIdx.x;
    for (int i = tid; i < 32 * En / 4; i += 256)
        ((float4*)&semb[0][0])[i] = ((const float4*)(emb + (size_t)vbase * En))[i];
    __syncthreads();
    int cq = tid & 31, vq = tid >> 5;
    int c = cbase + cq * 4, v0 = vq * 4;
    float acc[4][4];
    #pragma unroll
    for (int i = 0; i < 4; i++)
        #pragma unroll
        for (int j = 0; j < 4; j++) acc[i][j] = 0.0f;
    for (int e = 0; e < En; e++) {
        float4 w = *(const float4*)(Wi + (size_t)e * NG3 + c);
        #pragma unroll
        for (int vv = 0; vv < 4; vv++) {
            float a = semb[v0 + vv][e];
            acc[vv][0] = fmaf(a, w.x, acc[vv][0]);
            acc[vv][1] = fmaf(a, w.y, acc[vv][1]);
            acc[vv][2] = fmaf(a, w.z, acc[vv][2]);
            acc[vv][3] = fmaf(a, w.w, acc[vv][3]);
        }
    }
    float4 bb = make_float4(0.f, 0.f, 0.f, 0.f);
    if (c < 2 * Hn) bb = *(const float4*)(bh + c);
    #pragma unroll
    for (int vv = 0; vv < 4; vv++) {
        float4 o;
        o.x = acc[vv][0] + bb.x; o.y = acc[vv][1] + bb.y;
        o.z = acc[vv][2] + bb.z; o.w = acc[vv][3] + bb.w;
        *(float4*)(g_EW + (size_t)(vbase + v0 + vv) * NG3 + c) = o;
    }
}

// =================== weight prep: B fragments (bf16 hi/lo) ===================
// flat i = ((ks*2 + p)*3 + nt)*64 + l*2 + q
__global__ __launch_bounds__(256) void wprep_kernel(const float* __restrict__ Wh) {
    int nb = blockIdx.x;
    u32* dst = g_WF + (size_t)nb * BFRAG;
    for (int i = threadIdx.x; i < BFRAG; i += 256) {
        int ks = i / 384;
        int r = i - ks * 384;
        int p = r / 192; r -= p * 192;
        int nt = r / 64; r -= nt * 64;
        int l = r >> 1, q = r & 1;
        int k0 = ks * 16 + (l & 3) * 2 + q * 8;
        int n = nt * Hn + nb * NJb + (l >> 2);
        float w0 = Wh[(size_t)k0 * NG3 + n];
        float w1 = Wh[(size_t)(k0 + 1) * NG3 + n];
        unsigned short h0, h1;
        if (p == 0) { h0 = bf16r(w0); h1 = bf16r(w1); }
        else {
            h0 = bf16r(w0 - __bfloat162float(__ushort_as_bfloat16(bf16r(w0))));
            h1 = bf16r(w1 - __bfloat162float(__ushort_as_bfloat16(bf16r(w1))));
        }
        dst[i] = (u32)h0 | ((u32)h1 << 16);
    }
}

// =================== persistent mma.sync GRU ===================
// smem: B frags 96KB | Abuf0 48KB | Abuf1 48KB
extern __shared__ unsigned char smem_dyn[];

__global__ __launch_bounds__(128, 1) void gru_kernel(const int* __restrict__ tokens,
                                                     const float* __restrict__ bh) {
    __shared__ int stok[Bn];
    __shared__ float s_bh[NJb];

    int tid = threadIdx.x, bid = blockIdx.x;
    int l = tid & 31, w = tid >> 5;          // lane, warp (= m-tile)
    int j0 = bid * NJb;
    u32 sB = smem_u32(smem_dyn);
    u32 sA0 = sB + SM_B;

    // load B fragments (hi+lo) to smem once
    {
        const uint4* src = (const uint4*)(g_WF + (size_t)bid * BFRAG);
        uint4* d = (uint4*)(smem_dyn);
        for (int i = tid; i < BFRAG / 4; i += 128) d[i] = src[i];
    }
    if (tid < NJb) s_bh[tid] = bh[2 * Hn + j0 + tid];
    __syncthreads();

    // lane constants
    u32 lmoff = (u32)(((l & 7) + ((l >> 3) & 1) * 8) * 48 + (l >> 4) * 16);
    int grp = l >> 2, qd = l & 3;
    int b0 = w * 16 + grp, b1 = b0 + 8;
    int jj0 = qd * 2, jj1 = jj0 + 1;
    int colbase = (j0 & 8);                       // 0 or 8 within 16-wide tile
    int ksj = j0 >> 4;                            // kstep holding this block's cols

    for (int t = 0; t < Ln; t++) {
        const unsigned char* slab = g_YA + (size_t)t * SLAB;

        // stage chunk 0
        #pragma unroll 2
        for (int n = 0; n < 16; n++) {
            int ua = tid + n * 128;
            int ver = ua >> 10, u = ua & 1023;
            int r = u >> 1, half = u & 1;
            u32 sdst = sA0 + ver * 24576 + (r >> 6) * 3072 + ((r >> 4) & 3) * 768
                     + (r & 15) * 48 + half * 16;
            cp16(sdst, slab + ver * VERB + (size_t)u * 16);
        }
        cp_commit();
        if (tid < Bn) stok[tid] = tokens[tid * Ln + t];

        float acc[3][4];
        #pragma unroll
        for (int nt = 0; nt < 3; nt++)
            #pragma unroll
            for (int i = 0; i < 4; i++) acc[nt][i] = 0.0f;

        #pragma unroll 1
        for (int c = 0; c < 8; c++) {
            if (c < 7) {
                const unsigned char* cb = slab + (size_t)(c + 1) * 16384;
                u32 sbuf = sA0 + ((c + 1) & 1) * ABUFB;
                #pragma unroll 2
                for (int n = 0; n < 16; n++) {
                    int ua = tid + n * 128;
                    int ver = ua >> 10, u = ua & 1023;
                    int r = u >> 1, half = u & 1;
                    u32 sdst = sbuf + ver * 24576 + (r >> 6) * 3072 + ((r >> 4) & 3) * 768
                             + (r & 15) * 48 + half * 16;
                    cp16(sdst, cb + ver * VERB + (size_t)u * 16);
                }
                cp_commit();
                cp_wait<1>();
            } else {
                cp_wait<0>();
            }
            __syncthreads();

            u32 abuf = sA0 + (c & 1) * ABUFB;
            #pragma unroll
            for (int ksl = 0; ksl < 8; ksl++) {
                int kg = c * 8 + ksl;
                u32 tadr = abuf + ksl * 3072 + w * 768 + lmoff;
                u32 ahi[4], alo[4];
                ldm4(tadr, ahi[0], ahi[1], ahi[2], ahi[3]);
                ldm4(tadr + 24576, alo[0], alo[1], alo[2], alo[3]);
                #pragma unroll
                for (int nt = 0; nt < 3; nt++) {
                    uint2 bh2, bl2;
                    asm volatile("ld.shared.v2.u32 {%0,%1}, [%2];"
                        : "=r"(bh2.x), "=r"(bh2.y)
                        : "r"(sB + (u32)((((kg * 2 + 0) * 3 + nt) * 64 + l * 2) * 4)));
                    asm volatile("ld.shared.v2.u32 {%0,%1}, [%2];"
                        : "=r"(bl2.x), "=r"(bl2.y)
                        : "r"(sB + (u32)((((kg * 2 + 1) * 3 + nt) * 64 + l * 2) * 4)));
                    mma_bf16(acc[nt], ahi, bh2.x, bh2.y);
                    mma_bf16(acc[nt], ahi, bl2.x, bl2.y);
                    mma_bf16(acc[nt], alo, bh2.x, bh2.y);
                }
            }
            __syncthreads();
        }

        // ---- epilogue: all data thread-local ----
        {
            const float* hp_in = g_HP + (size_t)t * HB;
            float* hp_out = g_HP + (size_t)(t + 1) * HB;
            unsigned char* ya = g_YA + (size_t)(t + 1) * SLAB;
            #pragma unroll
            for (int half = 0; half < 2; half++) {
                int b = half ? b1 : b0;
                float sr0 = acc[0][half * 2], sr1 = acc[0][half * 2 + 1];
                float sz0 = acc[1][half * 2], sz1 = acc[1][half * 2 + 1];
                float sn0 = acc[2][half * 2], sn1 = acc[2][half * 2 + 1];
                const float* ew = g_EW + (size_t)stok[b] * NG3;
                int ja = j0 + jj0, jb = j0 + jj1;
                float r0 = 1.0f / (1.0f + __expf(-(ew[ja] + sr0)));
                float r1 = 1.0f / (1.0f + __expf(-(ew[jb] + sr1)));
                float z0 = 1.0f / (1.0f + __expf(-(ew[Hn + ja] + sz0)));
                float z1 = 1.0f / (1.0f + __expf(-(ew[Hn + jb] + sz1)));
                float n0 = tanhf(ew[2 * Hn + ja] + r0 * (sn0 + s_bh[jj0]));
                float n1 = tanhf(ew[2 * Hn + jb] + r1 * (sn1 + s_bh[jj1]));
                float2 hold = *(const float2*)(hp_in + (size_t)b * Hn + ja);
                float h0 = (1.0f - z0) * n0 + z0 * hold.x;
                float h1 = (1.0f - z1) * n1 + z1 * hold.y;
                *(float2*)(hp_out + (size_t)b * Hn + ja) = make_float2(h0, h1);
                unsigned short hi0 = bf16r(h0), hi1 = bf16r(h1);
                float f0 = h0 - __bfloat162float(__ushort_as_bfloat16(hi0));
                float f1 = h1 - __bfloat162float(__ushort_as_bfloat16(hi1));
                unsigned short lo0 = bf16r(f0), lo1 = bf16r(f1);
                u32 base = (u32)(ksj * 2048 + (b >> 4) * 512 + (b & 15) * 32
                         + (colbase + jj0) * 2);
                *(u32*)(ya + base)        = (u32)hi0 | ((u32)hi1 << 16);
                *(u32*)(ya + VERB + base) = (u32)lo0 | ((u32)lo1 << 16);
            }
        }

        // ---- grid barrier ----
        __syncthreads();
        if (tid == 0) {
            __threadfence();
            atomicAdd(&g_ctr, 1u);
            unsigned target = (unsigned)NBLK * (unsigned)(t + 1);
            while (*((volatile unsigned*)&g_ctr) < target) { }
        }
        __syncthreads();
    }
}

// =================== logits = Y @ Wout + bout (FFMA2, reads g_HP [t][b][j]) ===================
__device__ __forceinline__ u64 fma2(u64 a, u64 b, u64 c) {
    u64 d; asm("fma.rn.f32x2 %0, %1, %2, %3;" : "=l"(d) : "l"(a), "l"(b), "l"(c)); return d;
}
__device__ __forceinline__ u64 pack2(float x) {
    u64 d; asm("mov.b64 %0, {%1, %1};" : "=l"(d) : "f"(x)); return d;
}

__global__ __launch_bounds__(256, 1) void out_kernel(const float* __restrict__ Wout,
                                                     const float* __restrict__ bout,
                                                     float* __restrict__ out) {
    __shared__ float sY[32 * Bn];
    __shared__ float sW[32 * 128];
    int t = blockIdx.y;
    int vbase = blockIdx.x * 128;
    int tid = threadIdx.x;
    int bq = tid & 15, vq = tid >> 4;
    int bb = bq * 4, vv0 = vq * 8;
    const float* Yt = g_HP + (size_t)(t + 1) * HB;

    u64 acc2[4][4];
    #pragma unroll
    for (int i = 0; i < 4; i++)
        #pragma unroll
        for (int j = 0; j < 4; j++) acc2[i][j] = 0ull;

    for (int kc = 0; kc < Hn; kc += 32) {
        // stage Y tile transposed: sY[kk][b] <- HP[b][kc+kk]   (512 float4 total)
        #pragma unroll
        for (int n = 0; n < 2; n++) {
            int u = tid + n * 256;          // 0..511
            int b = u >> 3, kq = u & 7;     // b 0..63, kq 0..7
            float4 v4 = *(const float4*)(Yt + (size_t)b * Hn + kc + kq * 4);
            sY[(kq * 4 + 0) * Bn + b] = v4.x;
            sY[(kq * 4 + 1) * Bn + b] = v4.y;
            sY[(kq * 4 + 2) * Bn + b] = v4.z;
            sY[(kq * 4 + 3) * Bn + b] = v4.w;
        }
        for (int i = tid; i < 32 * 128 / 4; i += 256) {
            int kk = i >> 5, v4i = (i & 31) * 4;
            ((float4*)sW)[i] = *(const float4*)(Wout + (size_t)(kc + kk) * Vn + vbase + v4i);
        }
        __syncthreads();
        #pragma unroll 4
        for (int kk = 0; kk < 32; kk++) {
            float4 y4 = *(const float4*)(sY + kk * Bn + bb);
            ulonglong2 wA = *(const ulonglong2*)(sW + kk * 128 + vv0);
            ulonglong2 wB = *(const ulonglong2*)(sW + kk * 128 + vv0 + 4);
            u64 wp[4] = {wA.x, wA.y, wB.x, wB.y};
            u64 yy[4] = {pack2(y4.x), pack2(y4.y), pack2(y4.z), pack2(y4.w)};
            #pragma unroll
            for (int i = 0; i < 4; i++)
                #pragma unroll
                for (int j = 0; j < 4; j++)
                    acc2[i][j] = fma2(yy[i], wp[j], acc2[i][j]);
        }
        __syncthreads();
    }

    float4 ba = *(const float4*)(bout + vbase + vv0);
    float4 bbv = *(const float4*)(bout + vbase + vv0 + 4);
    float bs[8] = {ba.x, ba.y, ba.z, ba.w, bbv.x, bbv.y, bbv.z, bbv.w};
    #pragma unroll
    for (int i = 0; i < 4; i++) {
        float vals[8];
        #pragma unroll
        for (int j = 0; j < 4; j++) {
            unsigned lo, hi;
            asm("mov.b64 {%0, %1}, %2;" : "=r"(lo), "=r"(hi) : "l"(acc2[i][j]));
            vals[2 * j] = __uint_as_float(lo);
            vals[2 * j + 1] = __uint_as_float(hi);
        }
        float* po = out + (size_t)(bb + i) * Ln * Vn + (size_t)t * Vn + vbase + vv0;
        float4 o0, o1;
        o0.x = vals[0] + bs[0]; o0.y = vals[1] + bs[1];
        o0.z = vals[2] + bs[2]; o0.w = vals[3] + bs[3];
        o1.x = vals[4] + bs[4]; o1.y = vals[5] + bs[5];
        o1.z = vals[6] + bs[6]; o1.w = vals[7] + bs[7];
        *(float4*)(po + 0) = o0;
        *(float4*)(po + 4) = o1;
    }
}

// =================== launch ===================
extern "C" void kernel_launch(void* const* d_in, const int* in_sizes, int n_in,
                              void* d_out, int out_size) {
    const int*   tokens = (const int*)d_in[0];
    const float* emb    = (const float*)d_in[1];
    const float* Wi     = (const float*)d_in[2];
    const float* Wh     = (const float*)d_in[3];
    const float* bh     = (const float*)d_in[4];
    const float* Wout   = (const float*)d_in[5];
    const float* bout   = (const float*)d_in[6];
    float* out = (float*)d_out;

    cudaFuncSetAttribute(gru_kernel, cudaFuncAttributeMaxDynamicSharedMemorySize, SMEM_DYN);

    reset_kernel<<<64, 256>>>();
    ew_kernel<<<dim3(24, 8), 256>>>(emb, Wi, bh);
    wprep_kernel<<<NBLK, 256>>>(Wh);
    gru_kernel<<<NBLK, 128, SMEM_DYN>>>(tokens, bh);
    out_kernel<<<dim3(2, 256), 256>>>(Wout, bout, out);
}

// round 7
// speedup vs baseline: 1.0975x; 1.0975x over previous
#include <cuda_runtime.h>
#include <cuda_bf16.h>
#include <cstdint>

#define Bn 64
#define Ln 256
#define Vn 256
#define En 256
#define Hn 1024
#define NG3 3072
#define NBLK 128           // persistent blocks; each owns 8 hidden units
#define NJb 8
#define HB (Hn*Bn)
#define SLAB 262144        // bytes per h slab: [ver2][mt4][kc16][ks4][row16][32B]
#define VERB 131072
#define BFRAG 24576        // u32 B-fragment words per block (hi+lo)
#define SM_B 98304         // B fragments in smem (bytes)
#define WBUF 12288         // per-warp A double buffer (2 x 6144)
#define SMEM_DYN (SM_B + 8*WBUF)   // 196608 = 192KB

typedef unsigned int u32;
typedef unsigned long long u64;

__device__ float g_EW[Vn*NG3];                         // emb@Wi (+bh for r,z)
__device__ float g_HP[(size_t)(Ln+1)*HB];              // exact fp32 h, [t][b][j]
__device__ unsigned char g_YA[(size_t)(Ln+1)*SLAB];    // bf16 hi/lo tiled h slabs
__device__ u32 g_WF[(size_t)NBLK*BFRAG];               // B fragments per block
__device__ unsigned int g_ctr;

__device__ __forceinline__ u32 smem_u32(const void* p) {
    u32 a;
    asm("{ .reg .u64 t; cvta.to.shared.u64 t, %1; cvt.u32.u64 %0, t; }" : "=r"(a) : "l"(p));
    return a;
}
__device__ __forceinline__ void cp16(u32 dst, const void* src) {
    asm volatile("cp.async.cg.shared.global [%0], [%1], 16;" :: "r"(dst), "l"(src) : "memory");
}
__device__ __forceinline__ void cp_commit() {
    asm volatile("cp.async.commit_group;" ::: "memory");
}
template<int N> __device__ __forceinline__ void cp_wait() {
    asm volatile("cp.async.wait_group %0;" :: "n"(N) : "memory");
}
__device__ __forceinline__ void ldm4(u32 addr, u32& a0, u32& a1, u32& a2, u32& a3) {
    asm volatile("ldmatrix.sync.aligned.m8n8.x4.shared.b16 {%0,%1,%2,%3}, [%4];"
                 : "=r"(a0), "=r"(a1), "=r"(a2), "=r"(a3) : "r"(addr));
}
__device__ __forceinline__ void mma_bf16(float* c, const u32* a, u32 b0, u32 b1) {
    asm volatile("mma.sync.aligned.m16n8k16.row.col.f32.bf16.bf16.f32 "
        "{%0,%1,%2,%3}, {%4,%5,%6,%7}, {%8,%9}, {%0,%1,%2,%3};"
        : "+f"(c[0]), "+f"(c[1]), "+f"(c[2]), "+f"(c[3])
        : "r"(a[0]), "r"(a[1]), "r"(a[2]), "r"(a[3]), "r"(b0), "r"(b1));
}
__device__ __forceinline__ unsigned short bf16r(float x) {
    return __bfloat16_as_ushort(__float2bfloat16_rn(x));
}

// =================== reset ===================
__global__ void reset_kernel() {
    int tid = blockIdx.x * blockDim.x + threadIdx.x;
    int nt = gridDim.x * blockDim.x;
    for (int i = tid; i < HB; i += nt) g_HP[i] = 0.0f;
    for (int i = tid; i < SLAB / 4; i += nt) ((u32*)g_YA)[i] = 0u;
    if (tid == 0) g_ctr = 0u;
}

// =================== EW = embedding @ Wi (+ bh folded for r,z) ===================
__global__ __launch_bounds__(256) void ew_kernel(const float* __restrict__ emb,
                                                 const float* __restrict__ Wi,
                                                 const float* __restrict__ bh) {
    __shared__ float semb[32][En];
    int vbase = blockIdx.y * 32, cbase = blockIdx.x * 128, tid = threadIdx.x;
    for (int i = tid; i < 32 * En / 4; i += 256)
        ((float4*)&semb[0][0])[i] = ((const float4*)(emb + (size_t)vbase * En))[i];
    __syncthreads();
    int cq = tid & 31, vq = tid >> 5;
    int c = cbase + cq * 4, v0 = vq * 4;
    float acc[4][4];
    #pragma unroll
    for (int i = 0; i < 4; i++)
        #pragma unroll
        for (int j = 0; j < 4; j++) acc[i][j] = 0.0f;
    for (int e = 0; e < En; e++) {
        float4 w = *(const float4*)(Wi + (size_t)e * NG3 + c);
        #pragma unroll
        for (int vv = 0; vv < 4; vv++) {
            float a = semb[v0 + vv][e];
            acc[vv][0] = fmaf(a, w.x, acc[vv][0]);
            acc[vv][1] = fmaf(a, w.y, acc[vv][1]);
            acc[vv][2] = fmaf(a, w.z, acc[vv][2]);
            acc[vv][3] = fmaf(a, w.w, acc[vv][3]);
        }
    }
    float4 bb = make_float4(0.f, 0.f, 0.f, 0.f);
    if (c < 2 * Hn) bb = *(const float4*)(bh + c);
    #pragma unroll
    for (int vv = 0; vv < 4; vv++) {
        float4 o;
        o.x = acc[vv][0] + bb.x; o.y = acc[vv][1] + bb.y;
        o.z = acc[vv][2] + bb.z; o.w = acc[vv][3] + bb.w;
        *(float4*)(g_EW + (size_t)(vbase + v0 + vv) * NG3 + c) = o;
    }
}

// =================== weight prep: B fragments (bf16 hi/lo) ===================
// flat i = ((ks*2 + p)*3 + nt)*64 + l*2 + q
__global__ __launch_bounds__(256) void wprep_kernel(const float* __restrict__ Wh) {
    int nb = blockIdx.x;
    u32* dst = g_WF + (size_t)nb * BFRAG;
    for (int i = threadIdx.x; i < BFRAG; i += 256) {
        int ks = i / 384;
        int r = i - ks * 384;
        int p = r / 192; r -= p * 192;
        int nt = r / 64; r -= nt * 64;
        int l = r >> 1, q = r & 1;
        int k0 = ks * 16 + (l & 3) * 2 + q * 8;
        int n = nt * Hn + nb * NJb + (l >> 2);
        float w0 = Wh[(size_t)k0 * NG3 + n];
        float w1 = Wh[(size_t)(k0 + 1) * NG3 + n];
        unsigned short h0, h1;
        if (p == 0) { h0 = bf16r(w0); h1 = bf16r(w1); }
        else {
            h0 = bf16r(w0 - __bfloat162float(__ushort_as_bfloat16(bf16r(w0))));
            h1 = bf16r(w1 - __bfloat162float(__ushort_as_bfloat16(bf16r(w1))));
        }
        dst[i] = (u32)h0 | ((u32)h1 << 16);
    }
}

// =================== persistent mma.sync GRU ===================
// 256 threads = 8 warps; warp w: m-tile = w&3, k-half = w>>2 (k 0..511 / 512..1023)
// smem: B frags 96KB | 8 x warp-private A double buffer 12KB
extern __shared__ unsigned char smem_dyn[];

__global__ __launch_bounds__(256, 1) void gru_kernel(const int* __restrict__ tokens,
                                                     const float* __restrict__ bh) {
    __shared__ int stok[Bn];
    __shared__ float s_bh[NJb];
    __shared__ float s_part[4][32][13];   // half1 partials, padded stride 13

    int tid = threadIdx.x, bid = blockIdx.x;
    int l = tid & 31, w = tid >> 5;
    int mt = w & 3, half = w >> 2;
    int j0 = bid * NJb;
    u32 sB = smem_u32(smem_dyn);
    u32 wb = sB + SM_B + w * WBUF;

    // load B fragments (hi+lo) to smem once
    {
        const uint4* src = (const uint4*)(g_WF + (size_t)bid * BFRAG);
        uint4* d = (uint4*)(smem_dyn);
        for (int i = tid; i < BFRAG / 4; i += 256) d[i] = src[i];
    }
    if (tid < NJb) s_bh[tid] = bh[2 * Hn + j0 + tid];
    __syncthreads();

    // lane constants
    u32 lmoff = (u32)(((l & 7) + ((l >> 3) & 1) * 8) * 48 + (l >> 4) * 16);
    u32 strow = (u32)(((l >> 1) & 15) * 48 + (l & 1) * 16);
    int grp = l >> 2, qd = l & 3;
    int b0 = mt * 16 + grp, b1 = b0 + 8;
    int jj0 = qd * 2, jj1 = jj0 + 1;
    int colbase = (j0 & 8);
    int ksj = j0 >> 4;                        // global kstep of this block's cols
    int kcj = ksj >> 2, kslj = ksj & 3;

    for (int t = 0; t < Ln; t++) {
        const unsigned char* slab = g_YA + (size_t)t * SLAB;
        const unsigned char* mybase = slab + (size_t)mt * 32768;
        if (tid < Bn) stok[tid] = tokens[tid * Ln + t];

        // stage chunk 0 of my half (chunk index c = half*8 + cc, granule = 4 ks = 2KB/ver)
        {
            int c = half * 8;
            #pragma unroll
            for (int ver = 0; ver < 2; ver++)
                #pragma unroll
                for (int i = 0; i < 4; i++)
                    cp16(wb + ver * 3072 + (u32)i * 768 + strow,
                         mybase + (size_t)ver * VERB + c * 2048 + (i * 32 + l) * 16);
            cp_commit();
        }

        float acc[2][3][4];
        #pragma unroll
        for (int p = 0; p < 2; p++)
            #pragma unroll
            for (int nt = 0; nt < 3; nt++)
                #pragma unroll
                for (int i = 0; i < 4; i++) acc[p][nt][i] = 0.0f;

        #pragma unroll 1
        for (int cc = 0; cc < 8; cc++) {
            int c = half * 8 + cc;
            u32 buf = wb + (u32)(cc & 1) * 6144;
            if (cc < 7) {
                int cn = c + 1;
                u32 nbuf = wb + (u32)((cc + 1) & 1) * 6144;
                #pragma unroll
                for (int ver = 0; ver < 2; ver++)
                    #pragma unroll
                    for (int i = 0; i < 4; i++)
                        cp16(nbuf + ver * 3072 + (u32)i * 768 + strow,
                             mybase + (size_t)ver * VERB + cn * 2048 + (i * 32 + l) * 16);
                cp_commit();
                cp_wait<1>();
            } else {
                cp_wait<0>();
            }
            __syncwarp();

            #pragma unroll
            for (int ksl = 0; ksl < 4; ksl++) {
                int kg = c * 4 + ksl;
                int p = ksl & 1;
                u32 tadr = buf + (u32)ksl * 768 + lmoff;
                u32 ahi[4], alo[4];
                ldm4(tadr, ahi[0], ahi[1], ahi[2], ahi[3]);
                ldm4(tadr + 3072, alo[0], alo[1], alo[2], alo[3]);
                #pragma unroll
                for (int nt = 0; nt < 3; nt++) {
                    uint2 bh2, bl2;
                    asm volatile("ld.shared.v2.u32 {%0,%1}, [%2];"
                        : "=r"(bh2.x), "=r"(bh2.y)
                        : "r"(sB + (u32)((((kg * 2 + 0) * 3 + nt) * 64 + l * 2) * 4)));
                    asm volatile("ld.shared.v2.u32 {%0,%1}, [%2];"
                        : "=r"(bl2.x), "=r"(bl2.y)
                        : "r"(sB + (u32)((((kg * 2 + 1) * 3 + nt) * 64 + l * 2) * 4)));
                    mma_bf16(acc[p][nt], ahi, bh2.x, bh2.y);
                    mma_bf16(acc[p][nt], ahi, bl2.x, bl2.y);
                    mma_bf16(acc[p][nt], alo, bh2.x, bh2.y);
                }
            }
            __syncwarp();
        }

        // half-1 warps publish their partials (sum of parity sets)
        if (half == 1) {
            #pragma unroll
            for (int nt = 0; nt < 3; nt++)
                #pragma unroll
                for (int i = 0; i < 4; i++)
                    s_part[mt][l][nt * 4 + i] = acc[0][nt][i] + acc[1][nt][i];
        }
        __syncthreads();

        // ---- epilogue: half-0 warps combine + gates ----
        if (half == 0) {
            float ac[3][4];
            #pragma unroll
            for (int nt = 0; nt < 3; nt++)
                #pragma unroll
                for (int i = 0; i < 4; i++)
                    ac[nt][i] = acc[0][nt][i] + acc[1][nt][i] + s_part[mt][l][nt * 4 + i];

            const float* hp_in = g_HP + (size_t)t * HB;
            float* hp_out = g_HP + (size_t)(t + 1) * HB;
            unsigned char* ya = g_YA + (size_t)(t + 1) * SLAB;
            #pragma unroll
            for (int hf = 0; hf < 2; hf++) {
                int b = hf ? b1 : b0;
                float sr0 = ac[0][hf * 2], sr1 = ac[0][hf * 2 + 1];
                float sz0 = ac[1][hf * 2], sz1 = ac[1][hf * 2 + 1];
                float sn0 = ac[2][hf * 2], sn1 = ac[2][hf * 2 + 1];
                const float* ew = g_EW + (size_t)stok[b] * NG3;
                int ja = j0 + jj0, jb = j0 + jj1;
                float r0 = 1.0f / (1.0f + __expf(-(ew[ja] + sr0)));
                float r1 = 1.0f / (1.0f + __expf(-(ew[jb] + sr1)));
                float z0 = 1.0f / (1.0f + __expf(-(ew[Hn + ja] + sz0)));
                float z1 = 1.0f / (1.0f + __expf(-(ew[Hn + jb] + sz1)));
                float n0 = tanhf(ew[2 * Hn + ja] + r0 * (sn0 + s_bh[jj0]));
                float n1 = tanhf(ew[2 * Hn + jb] + r1 * (sn1 + s_bh[jj1]));
                float2 hold = *(const float2*)(hp_in + (size_t)b * Hn + ja);
                float h0 = (1.0f - z0) * n0 + z0 * hold.x;
                float h1 = (1.0f - z1) * n1 + z1 * hold.y;
                *(float2*)(hp_out + (size_t)b * Hn + ja) = make_float2(h0, h1);
                unsigned short hi0 = bf16r(h0), hi1 = bf16r(h1);
                float f0 = h0 - __bfloat162float(__ushort_as_bfloat16(hi0));
                float f1 = h1 - __bfloat162float(__ushort_as_bfloat16(hi1));
                unsigned short lo0 = bf16r(f0), lo1 = bf16r(f1);
                // slab layout: [ver][mt][kc][ksl][row16][32B]
                u32 base = (u32)((b >> 4) * 32768 + kcj * 2048 + kslj * 512
                         + (b & 15) * 32 + (colbase + jj0) * 2);
                *(u32*)(ya + base)        = (u32)hi0 | ((u32)hi1 << 16);
                *(u32*)(ya + VERB + base) = (u32)lo0 | ((u32)lo1 << 16);
            }
        }

        // ---- grid barrier ----
        __syncthreads();
        if (tid == 0) {
            __threadfence();
            atomicAdd(&g_ctr, 1u);
            unsigned target = (unsigned)NBLK * (unsigned)(t + 1);
            while (*((volatile unsigned*)&g_ctr) < target) { }
        }
        __syncthreads();
    }
}

// =================== logits = Y @ Wout + bout (FFMA2, reads g_HP [t][b][j]) ===================
__device__ __forceinline__ u64 fma2(u64 a, u64 b, u64 c) {
    u64 d; asm("fma.rn.f32x2 %0, %1, %2, %3;" : "=l"(d) : "l"(a), "l"(b), "l"(c)); return d;
}
__device__ __forceinline__ u64 pack2(float x) {
    u64 d; asm("mov.b64 %0, {%1, %1};" : "=l"(d) : "f"(x)); return d;
}

__global__ __launch_bounds__(256, 1) void out_kernel(const float* __restrict__ Wout,
                                                     const float* __restrict__ bout,
                                                     float* __restrict__ out) {
    __shared__ float sY[32 * Bn];
    __shared__ float sW[32 * 128];
    int t = blockIdx.y;
    int vbase = blockIdx.x * 128;
    int tid = threadIdx.x;
    int bq = tid & 15, vq = tid >> 4;
    int bb = bq * 4, vv0 = vq * 8;
    const float* Yt = g_HP + (size_t)(t + 1) * HB;

    u64 acc2[4][4];
    #pragma unroll
    for (int i = 0; i < 4; i++)
        #pragma unroll
        for (int j = 0; j < 4; j++) acc2[i][j] = 0ull;

    for (int kc = 0; kc < Hn; kc += 32) {
        #pragma unroll
        for (int n = 0; n < 2; n++) {
            int u = tid + n * 256;          // 0..511
            int b = u >> 3, kq = u & 7;     // b 0..63, kq 0..7
            float4 v4 = *(const float4*)(Yt + (size_t)b * Hn + kc + kq * 4);
            sY[(kq * 4 + 0) * Bn + b] = v4.x;
            sY[(kq * 4 + 1) * Bn + b] = v4.y;
            sY[(kq * 4 + 2) * Bn + b] = v4.z;
            sY[(kq * 4 + 3) * Bn + b] = v4.w;
        }
        for (int i = tid; i < 32 * 128 / 4; i += 256) {
            int kk = i >> 5, v4i = (i & 31) * 4;
            ((float4*)sW)[i] = *(const float4*)(Wout + (size_t)(kc + kk) * Vn + vbase + v4i);
        }
        __syncthreads();
        #pragma unroll 4
        for (int kk = 0; kk < 32; kk++) {
            float4 y4 = *(const float4*)(sY + kk * Bn + bb);
            ulonglong2 wA = *(const ulonglong2*)(sW + kk * 128 + vv0);
            ulonglong2 wB = *(const ulonglong2*)(sW + kk * 128 + vv0 + 4);
            u64 wp[4] = {wA.x, wA.y, wB.x, wB.y};
            u64 yy[4] = {pack2(y4.x), pack2(y4.y), pack2(y4.z), pack2(y4.w)};
            #pragma unroll
            for (int i = 0; i < 4; i++)
                #pragma unroll
                for (int j = 0; j < 4; j++)
                    acc2[i][j] = fma2(yy[i], wp[j], acc2[i][j]);
        }
        __syncthreads();
    }

    float4 ba = *(const float4*)(bout + vbase + vv0);
    float4 bbv = *(const float4*)(bout + vbase + vv0 + 4);
    float bs[8] = {ba.x, ba.y, ba.z, ba.w, bbv.x, bbv.y, bbv.z, bbv.w};
    #pragma unroll
    for (int i = 0; i < 4; i++) {
        float vals[8];
        #pragma unroll
        for (int j = 0; j < 4; j++) {
            unsigned lo, hi;
            asm("mov.b64 {%0, %1}, %2;" : "=r"(lo), "=r"(hi) : "l"(acc2[i][j]));
            vals[2 * j] = __uint_as_float(lo);
            vals[2 * j + 1] = __uint_as_float(hi);
        }
        float* po = out + (size_t)(bb + i) * Ln * Vn + (size_t)t * Vn + vbase + vv0;
        float4 o0, o1;
        o0.x = vals[0] + bs[0]; o0.y = vals[1] + bs[1];
        o0.z = vals[2] + bs[2]; o0.w = vals[3] + bs[3];
        o1.x = vals[4] + bs[4]; o1.y = vals[5] + bs[5];
        o1.z = vals[6] + bs[6]; o1.w = vals[7] + bs[7];
        *(float4*)(po + 0) = o0;
        *(float4*)(po + 4) = o1;
    }
}

// =================== launch ===================
extern "C" void kernel_launch(void* const* d_in, const int* in_sizes, int n_in,
                              void* d_out, int out_size) {
    const int*   tokens = (const int*)d_in[0];
    const float* emb    = (const float*)d_in[1];
    const float* Wi     = (const float*)d_in[2];
    const float* Wh     = (const float*)d_in[3];
    const float* bh     = (const float*)d_in[4];
    const float* Wout   = (const float*)d_in[5];
    const float* bout   = (const float*)d_in[6];
    float* out = (float*)d_out;

    cudaFuncSetAttribute(gru_kernel, cudaFuncAttributeMaxDynamicSharedMemorySize, SMEM_DYN);

    reset_kernel<<<64, 256>>>();
    ew_kernel<<<dim3(24, 8), 256>>>(emb, Wi, bh);
    wprep_kernel<<<NBLK, 256>>>(Wh);
    gru_kernel<<<NBLK, 256, SMEM_DYN>>>(tokens, bh);
    out_kernel<<<dim3(2, 256), 256>>>(Wout, bout, out);
}

// round 8
// speedup vs baseline: 1.1697x; 1.0658x over previous
#include <cuda_runtime.h>
#include <cuda_bf16.h>
#include <cstdint>

#define Bn 64
#define Ln 256
#define Vn 256
#define En 256
#define Hn 1024
#define NG3 3072
#define NBLK 128           // persistent blocks; each owns 8 hidden units
#define NJb 8
#define HB (Hn*Bn)
#define SLAB 262144        // bytes per h slab: [ver2][mt4][kc16][ks4][row16][32B]
#define VERB 131072
#define BFRAG 24576        // u32 B-fragment words per block (hi+lo)
#define SM_B 98304         // B fragments in smem (bytes)
#define WBUF 12288         // per-warp A double buffer (2 x 6144)
#define SMEM_DYN (SM_B + 8*WBUF)   // 196608 = 192KB

typedef unsigned int u32;
typedef unsigned long long u64;

__device__ float g_EW[Vn*NG3];                         // emb@Wi (+bh for r,z)
__device__ float g_HP[(size_t)(Ln+1)*HB];              // exact fp32 h, [t][b][j]
__device__ unsigned char g_YA[(size_t)(Ln+1)*SLAB];    // bf16 hi/lo tiled h slabs
__device__ u32 g_WF[(size_t)NBLK*BFRAG];               // B fragments per block
__device__ unsigned int g_ctr;
__device__ volatile unsigned int g_go;

__device__ __forceinline__ u32 smem_u32(const void* p) {
    u32 a;
    asm("{ .reg .u64 t; cvta.to.shared.u64 t, %1; cvt.u32.u64 %0, t; }" : "=r"(a) : "l"(p));
    return a;
}
__device__ __forceinline__ void cp16(u32 dst, const void* src) {
    asm volatile("cp.async.cg.shared.global [%0], [%1], 16;" :: "r"(dst), "l"(src) : "memory");
}
__device__ __forceinline__ void cp_commit() {
    asm volatile("cp.async.commit_group;" ::: "memory");
}
template<int N> __device__ __forceinline__ void cp_wait() {
    asm volatile("cp.async.wait_group %0;" :: "n"(N) : "memory");
}
__device__ __forceinline__ void ldm4(u32 addr, u32& a0, u32& a1, u32& a2, u32& a3) {
    asm volatile("ldmatrix.sync.aligned.m8n8.x4.shared.b16 {%0,%1,%2,%3}, [%4];"
                 : "=r"(a0), "=r"(a1), "=r"(a2), "=r"(a3) : "r"(addr));
}
__device__ __forceinline__ void mma_bf16(float* c, const u32* a, u32 b0, u32 b1) {
    asm volatile("mma.sync.aligned.m16n8k16.row.col.f32.bf16.bf16.f32 "
        "{%0,%1,%2,%3}, {%4,%5,%6,%7}, {%8,%9}, {%0,%1,%2,%3};"
        : "+f"(c[0]), "+f"(c[1]), "+f"(c[2]), "+f"(c[3])
        : "r"(a[0]), "r"(a[1]), "r"(a[2]), "r"(a[3]), "r"(b0), "r"(b1));
}
__device__ __forceinline__ unsigned short bf16r(float x) {
    return __bfloat16_as_ushort(__float2bfloat16_rn(x));
}

// =================== reset ===================
__global__ void reset_kernel() {
    int tid = blockIdx.x * blockDim.x + threadIdx.x;
    int nt = gridDim.x * blockDim.x;
    for (int i = tid; i < HB; i += nt) g_HP[i] = 0.0f;
    for (int i = tid; i < SLAB / 4; i += nt) ((u32*)g_YA)[i] = 0u;
    if (tid == 0) { g_ctr = 0u; g_go = 0u; }
}

// =================== EW = embedding @ Wi (+ bh folded for r,z) ===================
__global__ __launch_bounds__(256) void ew_kernel(const float* __restrict__ emb,
                                                 const float* __restrict__ Wi,
                                                 const float* __restrict__ bh) {
    __shared__ float semb[32][En];
    int vbase = blockIdx.y * 32, cbase = blockIdx.x * 128, tid = threadIdx.x;
    for (int i = tid; i < 32 * En / 4; i += 256)
        ((float4*)&semb[0][0])[i] = ((const float4*)(emb + (size_t)vbase * En))[i];
    __syncthreads();
    int cq = tid & 31, vq = tid >> 5;
    int c = cbase + cq * 4, v0 = vq * 4;
    float acc[4][4];
    #pragma unroll
    for (int i = 0; i < 4; i++)
        #pragma unroll
        for (int j = 0; j < 4; j++) acc[i][j] = 0.0f;
    for (int e = 0; e < En; e++) {
        float4 w = *(const float4*)(Wi + (size_t)e * NG3 + c);
        #pragma unroll
        for (int vv = 0; vv < 4; vv++) {
            float a = semb[v0 + vv][e];
            acc[vv][0] = fmaf(a, w.x, acc[vv][0]);
            acc[vv][1] = fmaf(a, w.y, acc[vv][1]);
            acc[vv][2] = fmaf(a, w.z, acc[vv][2]);
            acc[vv][3] = fmaf(a, w.w, acc[vv][3]);
        }
    }
    float4 bb = make_float4(0.f, 0.f, 0.f, 0.f);
    if (c < 2 * Hn) bb = *(const float4*)(bh + c);
    #pragma unroll
    for (int vv = 0; vv < 4; vv++) {
        float4 o;
        o.x = acc[vv][0] + bb.x; o.y = acc[vv][1] + bb.y;
        o.z = acc[vv][2] + bb.z; o.w = acc[vv][3] + bb.w;
        *(float4*)(g_EW + (size_t)(vbase + v0 + vv) * NG3 + c) = o;
    }
}

// =================== weight prep: B fragments (bf16 hi/lo), lane-vectorized ===================
// i = ((kg*3 + nt)*32 + l)*4 + c,  c: (p = c>>1, q = c&1)
__global__ __launch_bounds__(256) void wprep_kernel(const float* __restrict__ Wh) {
    int nb = blockIdx.x;
    u32* dst = g_WF + (size_t)nb * BFRAG;
    for (int i = threadIdx.x; i < BFRAG; i += 256) {
        int kg = i / 384;
        int r = i - kg * 384;
        int nt = r >> 7; r &= 127;
        int l = r >> 2, c = r & 3;
        int p = c >> 1, q = c & 1;
        int k0 = kg * 16 + (l & 3) * 2 + q * 8;
        int n = nt * Hn + nb * NJb + (l >> 2);
        float w0 = Wh[(size_t)k0 * NG3 + n];
        float w1 = Wh[(size_t)(k0 + 1) * NG3 + n];
        unsigned short h0, h1;
        if (p == 0) { h0 = bf16r(w0); h1 = bf16r(w1); }
        else {
            h0 = bf16r(w0 - __bfloat162float(__ushort_as_bfloat16(bf16r(w0))));
            h1 = bf16r(w1 - __bfloat162float(__ushort_as_bfloat16(bf16r(w1))));
        }
        dst[i] = (u32)h0 | ((u32)h1 << 16);
    }
}

// =================== persistent mma.sync GRU ===================
// 256 threads = 8 warps; warp w: m-tile = w&3, k-half = w>>2
// smem: B frags 96KB | 8 x warp-private A double buffer 12KB
extern __shared__ unsigned char smem_dyn[];

__global__ __launch_bounds__(256, 1) void gru_kernel(const int* __restrict__ tokens,
                                                     const float* __restrict__ bh) {
    __shared__ float s_bh[NJb];
    __shared__ float s_part[4][32][13];   // half1 partials, padded stride 13

    int tid = threadIdx.x, bid = blockIdx.x;
    int l = tid & 31, w = tid >> 5;
    int mt = w & 3, half = w >> 2;
    int j0 = bid * NJb;
    u32 sB = smem_u32(smem_dyn);
    u32 wb = sB + SM_B + w * WBUF;

    // load B fragments (hi+lo) to smem once
    {
        const uint4* src = (const uint4*)(g_WF + (size_t)bid * BFRAG);
        uint4* d = (uint4*)(smem_dyn);
        for (int i = tid; i < BFRAG / 4; i += 256) d[i] = src[i];
    }
    if (tid < NJb) s_bh[tid] = bh[2 * Hn + j0 + tid];
    __syncthreads();

    // lane constants
    u32 lmoff = (u32)(((l & 7) + ((l >> 3) & 1) * 8) * 48 + (l >> 4) * 16);
    u32 strow = (u32)(((l >> 1) & 15) * 48 + (l & 1) * 16);
    int grp = l >> 2, qd = l & 3;
    int b0 = mt * 16 + grp, b1 = b0 + 8;
    int jj0 = qd * 2, jj1 = jj0 + 1;
    int colbase = (j0 & 8);
    int ksj = j0 >> 4;
    int kcj = ksj >> 2, kslj = ksj & 3;
    int ja = j0 + jj0;

    for (int t = 0; t < Ln; t++) {
        const unsigned char* slab = g_YA + (size_t)t * SLAB;
        const unsigned char* mybase = slab + (size_t)mt * 32768;

        // stage chunk 0 of my half FIRST (mainloop depends on it)
        {
            int c = half * 8;
            #pragma unroll
            for (int ver = 0; ver < 2; ver++)
                #pragma unroll
                for (int i = 0; i < 4; i++)
                    cp16(wb + ver * 3072 + (u32)i * 768 + strow,
                         mybase + (size_t)ver * VERB + c * 2048 + (i * 32 + l) * 16);
            cp_commit();
        }

        // epilogue-data prefetch (half-0 warps): issued now, consumed after mainloop
        float2 ewr0, ewz0, ewn0, ewr1, ewz1, ewn1, hold0, hold1;
        if (half == 0) {
            int tok0 = __ldg(tokens + b0 * Ln + t);
            int tok1 = __ldg(tokens + b1 * Ln + t);
            const float* e0 = g_EW + (size_t)tok0 * NG3;
            const float* e1 = g_EW + (size_t)tok1 * NG3;
            ewr0 = *(const float2*)(e0 + ja);
            ewz0 = *(const float2*)(e0 + Hn + ja);
            ewn0 = *(const float2*)(e0 + 2 * Hn + ja);
            ewr1 = *(const float2*)(e1 + ja);
            ewz1 = *(const float2*)(e1 + Hn + ja);
            ewn1 = *(const float2*)(e1 + 2 * Hn + ja);
            const float* hp_in = g_HP + (size_t)t * HB;
            hold0 = *(const float2*)(hp_in + (size_t)b0 * Hn + ja);
            hold1 = *(const float2*)(hp_in + (size_t)b1 * Hn + ja);
        }

        float acc[2][3][4];
        #pragma unroll
        for (int p = 0; p < 2; p++)
            #pragma unroll
            for (int nt = 0; nt < 3; nt++)
                #pragma unroll
                for (int i = 0; i < 4; i++) acc[p][nt][i] = 0.0f;

        #pragma unroll 1
        for (int cc = 0; cc < 8; cc++) {
            int c = half * 8 + cc;
            u32 buf = wb + (u32)(cc & 1) * 6144;
            if (cc < 7) {
                int cn = c + 1;
                u32 nbuf = wb + (u32)((cc + 1) & 1) * 6144;
                #pragma unroll
                for (int ver = 0; ver < 2; ver++)
                    #pragma unroll
                    for (int i = 0; i < 4; i++)
                        cp16(nbuf + ver * 3072 + (u32)i * 768 + strow,
                             mybase + (size_t)ver * VERB + cn * 2048 + (i * 32 + l) * 16);
                cp_commit();
                cp_wait<1>();
            } else {
                cp_wait<0>();
            }
            __syncwarp();

            #pragma unroll
            for (int ksl = 0; ksl < 4; ksl++) {
                int kg = c * 4 + ksl;
                int p = ksl & 1;
                u32 tadr = buf + (u32)ksl * 768 + lmoff;
                u32 ahi[4], alo[4];
                ldm4(tadr, ahi[0], ahi[1], ahi[2], ahi[3]);
                ldm4(tadr + 3072, alo[0], alo[1], alo[2], alo[3]);
                #pragma unroll
                for (int nt = 0; nt < 3; nt++) {
                    u32 bw0, bw1, bw2, bw3;   // p0q0, p0q1, p1q0, p1q1
                    asm volatile("ld.shared.v4.u32 {%0,%1,%2,%3}, [%4];"
                        : "=r"(bw0), "=r"(bw1), "=r"(bw2), "=r"(bw3)
                        : "r"(sB + (u32)((((kg * 3 + nt) * 32 + l) * 4) * 4)));
                    mma_bf16(acc[p][nt], ahi, bw0, bw1);
                    mma_bf16(acc[p][nt], ahi, bw2, bw3);
                    mma_bf16(acc[p][nt], alo, bw0, bw1);
                }
            }
            __syncwarp();
        }

        // half-1 warps publish their partials (sum of parity sets)
        if (half == 1) {
            #pragma unroll
            for (int nt = 0; nt < 3; nt++)
                #pragma unroll
                for (int i = 0; i < 4; i++)
                    s_part[mt][l][nt * 4 + i] = acc[0][nt][i] + acc[1][nt][i];
        }
        __syncthreads();

        // ---- epilogue: half-0 warps combine + gates (all operands prefetched) ----
        if (half == 0) {
            float ac[3][4];
            #pragma unroll
            for (int nt = 0; nt < 3; nt++)
                #pragma unroll
                for (int i = 0; i < 4; i++)
                    ac[nt][i] = acc[0][nt][i] + acc[1][nt][i] + s_part[mt][l][nt * 4 + i];

            float* hp_out = g_HP + (size_t)(t + 1) * HB;
            unsigned char* ya = g_YA + (size_t)(t + 1) * SLAB;
            #pragma unroll
            for (int hf = 0; hf < 2; hf++) {
                int b = hf ? b1 : b0;
                float2 er = hf ? ewr1 : ewr0;
                float2 ez = hf ? ewz1 : ewz0;
                float2 en = hf ? ewn1 : ewn0;
                float2 hold = hf ? hold1 : hold0;
                float sr0 = ac[0][hf * 2], sr1 = ac[0][hf * 2 + 1];
                float sz0 = ac[1][hf * 2], sz1 = ac[1][hf * 2 + 1];
                float sn0 = ac[2][hf * 2], sn1 = ac[2][hf * 2 + 1];
                float r0 = 1.0f / (1.0f + __expf(-(er.x + sr0)));
                float r1 = 1.0f / (1.0f + __expf(-(er.y + sr1)));
                float z0 = 1.0f / (1.0f + __expf(-(ez.x + sz0)));
                float z1 = 1.0f / (1.0f + __expf(-(ez.y + sz1)));
                float n0 = tanhf(en.x + r0 * (sn0 + s_bh[jj0]));
                float n1 = tanhf(en.y + r1 * (sn1 + s_bh[jj1]));
                float h0 = (1.0f - z0) * n0 + z0 * hold.x;
                float h1 = (1.0f - z1) * n1 + z1 * hold.y;
                *(float2*)(hp_out + (size_t)b * Hn + ja) = make_float2(h0, h1);
                unsigned short hi0 = bf16r(h0), hi1 = bf16r(h1);
                float f0 = h0 - __bfloat162float(__ushort_as_bfloat16(hi0));
                float f1 = h1 - __bfloat162float(__ushort_as_bfloat16(hi1));
                unsigned short lo0 = bf16r(f0), lo1 = bf16r(f1);
                u32 base = (u32)((b >> 4) * 32768 + kcj * 2048 + kslj * 512
                         + (b & 15) * 32 + (colbase + jj0) * 2);
                *(u32*)(ya + base)        = (u32)hi0 | ((u32)hi1 << 16);
                *(u32*)(ya + VERB + base) = (u32)lo0 | ((u32)lo1 << 16);
            }
        }

        // ---- grid barrier: atomic arrive, flag release, flag spin ----
        __syncthreads();
        if (tid == 0) {
            __threadfence();
            unsigned r = atomicAdd(&g_ctr, 1u);
            unsigned target = (unsigned)NBLK * (unsigned)(t + 1);
            if (r == target - 1u) {
                g_go = target;            // release: fence above ordered all writes
            }
            while (g_go < target) { }
            __threadfence();
        }
        __syncthreads();
    }
}

// =================== logits = Y @ Wout + bout (FFMA2, reads g_HP [t][b][j]) ===================
__device__ __forceinline__ u64 fma2(u64 a, u64 b, u64 c) {
    u64 d; asm("fma.rn.f32x2 %0, %1, %2, %3;" : "=l"(d) : "l"(a), "l"(b), "l"(c)); return d;
}
__device__ __forceinline__ u64 pack2(float x) {
    u64 d; asm("mov.b64 %0, {%1, %1};" : "=l"(d) : "f"(x)); return d;
}

__global__ __launch_bounds__(256, 1) void out_kernel(const float* __restrict__ Wout,
                                                     const float* __restrict__ bout,
                                                     float* __restrict__ out) {
    __shared__ float sY[32 * Bn];
    __shared__ float sW[32 * 128];
    int t = blockIdx.y;
    int vbase = blockIdx.x * 128;
    int tid = threadIdx.x;
    int bq = tid & 15, vq = tid >> 4;
    int bb = bq * 4, vv0 = vq * 8;
    const float* Yt = g_HP + (size_t)(t + 1) * HB;

    u64 acc2[4][4];
    #pragma unroll
    for (int i = 0; i < 4; i++)
        #pragma unroll
        for (int j = 0; j < 4; j++) acc2[i][j] = 0ull;

    for (int kc = 0; kc < Hn; kc += 32) {
        #pragma unroll
        for (int n = 0; n < 2; n++) {
            int u = tid + n * 256;          // 0..511
            int b = u >> 3, kq = u & 7;     // b 0..63, kq 0..7
            float4 v4 = *(const float4*)(Yt + (size_t)b * Hn + kc + kq * 4);
            sY[(kq * 4 + 0) * Bn + b] = v4.x;
            sY[(kq * 4 + 1) * Bn + b] = v4.y;
            sY[(kq * 4 + 2) * Bn + b] = v4.z;
            sY[(kq * 4 + 3) * Bn + b] = v4.w;
        }
        for (int i = tid; i < 32 * 128 / 4; i += 256) {
            int kk = i >> 5, v4i = (i & 31) * 4;
            ((float4*)sW)[i] = *(const float4*)(Wout + (size_t)(kc + kk) * Vn + vbase + v4i);
        }
        __syncthreads();
        #pragma unroll 4
        for (int kk = 0; kk < 32; kk++) {
            float4 y4 = *(const float4*)(sY + kk * Bn + bb);
            ulonglong2 wA = *(const ulonglong2*)(sW + kk * 128 + vv0);
            ulonglong2 wB = *(const ulonglong2*)(sW + kk * 128 + vv0 + 4);
            u64 wp[4] = {wA.x, wA.y, wB.x, wB.y};
            u64 yy[4] = {pack2(y4.x), pack2(y4.y), pack2(y4.z), pack2(y4.w)};
            #pragma unroll
            for (int i = 0; i < 4; i++)
                #pragma unroll
                for (int j = 0; j < 4; j++)
                    acc2[i][j] = fma2(yy[i], wp[j], acc2[i][j]);
        }
        __syncthreads();
    }

    float4 ba = *(const float4*)(bout + vbase + vv0);
    float4 bbv = *(const float4*)(bout + vbase + vv0 + 4);
    float bs[8] = {ba.x, ba.y, ba.z, ba.w, bbv.x, bbv.y, bbv.z, bbv.w};
    #pragma unroll
    for (int i = 0; i < 4; i++) {
        float vals[8];
        #pragma unroll
        for (int j = 0; j < 4; j++) {
            unsigned lo, hi;
            asm("mov.b64 {%0, %1}, %2;" : "=r"(lo), "=r"(hi) : "l"(acc2[i][j]));
            vals[2 * j] = __uint_as_float(lo);
            vals[2 * j + 1] = __uint_as_float(hi);
        }
        float* po = out + (size_t)(bb + i) * Ln * Vn + (size_t)t * Vn + vbase + vv0;
        float4 o0, o1;
        o0.x = vals[0] + bs[0]; o0.y = vals[1] + bs[1];
        o0.z = vals[2] + bs[2]; o0.w = vals[3] + bs[3];
        o1.x = vals[4] + bs[4]; o1.y = vals[5] + bs[5];
        o1.z = vals[6] + bs[6]; o1.w = vals[7] + bs[7];
        *(float4*)(po + 0) = o0;
        *(float4*)(po + 4) = o1;
    }
}

// =================== launch ===================
extern "C" void kernel_launch(void* const* d_in, const int* in_sizes, int n_in,
                              void* d_out, int out_size) {
    const int*   tokens = (const int*)d_in[0];
    const float* emb    = (const float*)d_in[1];
    const float* Wi     = (const float*)d_in[2];
    const float* Wh     = (const float*)d_in[3];
    const float* bh     = (const float*)d_in[4];
    const float* Wout   = (const float*)d_in[5];
    const float* bout   = (const float*)d_in[6];
    float* out = (float*)d_out;

    cudaFuncSetAttribute(gru_kernel, cudaFuncAttributeMaxDynamicSharedMemorySize, SMEM_DYN);

    reset_kernel<<<64, 256>>>();
    ew_kernel<<<dim3(24, 8), 256>>>(emb, Wi, bh);
    wprep_kernel<<<NBLK, 256>>>(Wh);
    gru_kernel<<<NBLK, 256, SMEM_DYN>>>(tokens, bh);
    out_kernel<<<dim3(2, 256), 256>>>(Wout, bout, out);
}

// round 9
// speedup vs baseline: 2.1708x; 1.8558x over previous
#include <cuda_runtime.h>
#include <cuda_bf16.h>
#include <cstdint>

#define Bn 64
#define Ln 256
#define Vn 256
#define En 256
#define Hn 1024
#define NG3 3072
#define NBLK 128           // persistent blocks; each owns 8 hidden units
#define NJb 8
#define HB (Hn*Bn)
#define SLAB 262144        // h slab: [ver2][mt4][ks64][lane32][16B]
#define VERB 131072
#define BFRAG 24576        // u32 B-fragment words per block (hi+lo)
#define SM_B 98304         // B fragments in smem (bytes)
#define SMEM_DYN SM_B

typedef unsigned int u32;
typedef unsigned long long u64;

__device__ float g_EW[Vn*NG3];                         // emb@Wi (+bh for r,z)
__device__ float g_HP[(size_t)(Ln+1)*HB];              // exact fp32 h, [t][b][j]
__device__ unsigned char g_YA[(size_t)(Ln+1)*SLAB];    // bf16 hi/lo fragment-order h
__device__ u32 g_WF[(size_t)NBLK*BFRAG];               // B fragments per block
__device__ unsigned int g_ctr;
__device__ volatile unsigned int g_go;

__device__ __forceinline__ u32 smem_u32(const void* p) {
    u32 a;
    asm("{ .reg .u64 t; cvta.to.shared.u64 t, %1; cvt.u32.u64 %0, t; }" : "=r"(a) : "l"(p));
    return a;
}
__device__ __forceinline__ void mma_bf16(float* c, const u32* a, u32 b0, u32 b1) {
    asm volatile("mma.sync.aligned.m16n8k16.row.col.f32.bf16.bf16.f32 "
        "{%0,%1,%2,%3}, {%4,%5,%6,%7}, {%8,%9}, {%0,%1,%2,%3};"
        : "+f"(c[0]), "+f"(c[1]), "+f"(c[2]), "+f"(c[3])
        : "r"(a[0]), "r"(a[1]), "r"(a[2]), "r"(a[3]), "r"(b0), "r"(b1));
}
__device__ __forceinline__ unsigned short bf16r(float x) {
    return __bfloat16_as_ushort(__float2bfloat16_rn(x));
}

// =================== reset ===================
__global__ void reset_kernel() {
    int tid = blockIdx.x * blockDim.x + threadIdx.x;
    int nt = gridDim.x * blockDim.x;
    for (int i = tid; i < HB; i += nt) g_HP[i] = 0.0f;
    for (int i = tid; i < SLAB / 4; i += nt) ((u32*)g_YA)[i] = 0u;
    if (tid == 0) { g_ctr = 0u; g_go = 0u; }
}

// =================== EW = embedding @ Wi (+ bh folded for r,z) ===================
__global__ __launch_bounds__(256) void ew_kernel(const float* __restrict__ emb,
                                                 const float* __restrict__ Wi,
                                                 const float* __restrict__ bh) {
    __shared__ float semb[32][En];
    int vbase = blockIdx.y * 32, cbase = blockIdx.x * 128, tid = threadIdx.x;
    for (int i = tid; i < 32 * En / 4; i += 256)
        ((float4*)&semb[0][0])[i] = ((const float4*)(emb + (size_t)vbase * En))[i];
    __syncthreads();
    int cq = tid & 31, vq = tid >> 5;
    int c = cbase + cq * 4, v0 = vq * 4;
    float acc[4][4];
    #pragma unroll
    for (int i = 0; i < 4; i++)
        #pragma unroll
        for (int j = 0; j < 4; j++) acc[i][j] = 0.0f;
    for (int e = 0; e < En; e++) {
        float4 w = *(const float4*)(Wi + (size_t)e * NG3 + c);
        #pragma unroll
        for (int vv = 0; vv < 4; vv++) {
            float a = semb[v0 + vv][e];
            acc[vv][0] = fmaf(a, w.x, acc[vv][0]);
            acc[vv][1] = fmaf(a, w.y, acc[vv][1]);
            acc[vv][2] = fmaf(a, w.z, acc[vv][2]);
            acc[vv][3] = fmaf(a, w.w, acc[vv][3]);
        }
    }
    float4 bb = make_float4(0.f, 0.f, 0.f, 0.f);
    if (c < 2 * Hn) bb = *(const float4*)(bh + c);
    #pragma unroll
    for (int vv = 0; vv < 4; vv++) {
        float4 o;
        o.x = acc[vv][0] + bb.x; o.y = acc[vv][1] + bb.y;
        o.z = acc[vv][2] + bb.z; o.w = acc[vv][3] + bb.w;
        *(float4*)(g_EW + (size_t)(vbase + v0 + vv) * NG3 + c) = o;
    }
}

// =================== weight prep: B fragments (bf16 hi/lo), lane-vectorized ===================
// i = ((kg*3 + nt)*32 + l)*4 + c,  c: (p = c>>1, q = c&1)
__global__ __launch_bounds__(256) void wprep_kernel(const float* __restrict__ Wh) {
    int nb = blockIdx.x;
    u32* dst = g_WF + (size_t)nb * BFRAG;
    for (int i = threadIdx.x; i < BFRAG; i += 256) {
        int kg = i / 384;
        int r = i - kg * 384;
        int nt = r >> 7; r &= 127;
        int l = r >> 2, c = r & 3;
        int p = c >> 1, q = c & 1;
        int k0 = kg * 16 + (l & 3) * 2 + q * 8;
        int n = nt * Hn + nb * NJb + (l >> 2);
        float w0 = Wh[(size_t)k0 * NG3 + n];
        float w1 = Wh[(size_t)(k0 + 1) * NG3 + n];
        unsigned short h0, h1;
        if (p == 0) { h0 = bf16r(w0); h1 = bf16r(w1); }
        else {
            h0 = bf16r(w0 - __bfloat162float(__ushort_as_bfloat16(bf16r(w0))));
            h1 = bf16r(w1 - __bfloat162float(__ushort_as_bfloat16(bf16r(w1))));
        }
        dst[i] = (u32)h0 | ((u32)h1 << 16);
    }
}

// =================== persistent mma.sync GRU ===================
// 512 threads = 16 warps; warp w: m-tile = w&3, k-quarter = w>>2 (256 k each)
// A: direct LDG.128 from fragment-ordered slab; B: smem-resident fragments.
extern __shared__ unsigned char smem_dyn[];

__global__ __launch_bounds__(512, 1) void gru_kernel(const int* __restrict__ tokens,
                                                     const float* __restrict__ bh) {
    __shared__ float s_bh[NJb];
    __shared__ float s_part[3][4][32][13];   // kq 1..3 partials, padded

    int tid = threadIdx.x, bid = blockIdx.x;
    int l = tid & 31, w = tid >> 5;
    int mt = w & 3, kq = w >> 2;
    int j0 = bid * NJb;
    u32 sB = smem_u32(smem_dyn);

    // load B fragments (hi+lo) to smem once
    {
        const uint4* src = (const uint4*)(g_WF + (size_t)bid * BFRAG);
        uint4* d = (uint4*)(smem_dyn);
        for (int i = tid; i < BFRAG / 4; i += 512) d[i] = src[i];
    }
    if (tid < NJb) s_bh[tid] = bh[2 * Hn + j0 + tid];
    __syncthreads();

    // lane constants
    int grp = l >> 2, qd = l & 3;
    int b0 = mt * 16 + grp, b1 = b0 + 8;
    int jj0 = qd * 2, jj1 = jj0 + 1;
    int colbase = (j0 & 8);
    int ksj = j0 >> 4;
    int ja = j0 + jj0;

    for (int t = 0; t < Ln; t++) {
        const unsigned char* slab = g_YA + (size_t)t * SLAB;
        const unsigned char* ah = slab + (size_t)mt * 32768 + (size_t)kq * 8192 + (size_t)l * 16;

        // prologue: start A ring (depth 4)
        uint4 rh[4], rl[4];
        #pragma unroll
        for (int p = 0; p < 4; p++) {
            rh[p] = *(const uint4*)(ah + p * 512);
            rl[p] = *(const uint4*)(ah + VERB + p * 512);
        }

        // epilogue-data prefetch (kq==0 warps): issued now, consumed after mainloop
        float2 ewr0, ewz0, ewn0, ewr1, ewz1, ewn1, hold0, hold1;
        if (kq == 0) {
            int tok0 = __ldg(tokens + b0 * Ln + t);
            int tok1 = __ldg(tokens + b1 * Ln + t);
            const float* e0 = g_EW + (size_t)tok0 * NG3;
            const float* e1 = g_EW + (size_t)tok1 * NG3;
            ewr0 = *(const float2*)(e0 + ja);
            ewz0 = *(const float2*)(e0 + Hn + ja);
            ewn0 = *(const float2*)(e0 + 2 * Hn + ja);
            ewr1 = *(const float2*)(e1 + ja);
            ewz1 = *(const float2*)(e1 + Hn + ja);
            ewn1 = *(const float2*)(e1 + 2 * Hn + ja);
            const float* hp_in = g_HP + (size_t)t * HB;
            hold0 = *(const float2*)(hp_in + (size_t)b0 * Hn + ja);
            hold1 = *(const float2*)(hp_in + (size_t)b1 * Hn + ja);
        }

        float acc[2][3][4];
        #pragma unroll
        for (int p = 0; p < 2; p++)
            #pragma unroll
            for (int nt = 0; nt < 3; nt++)
                #pragma unroll
                for (int i = 0; i < 4; i++) acc[p][nt][i] = 0.0f;

        #pragma unroll
        for (int ks = 0; ks < 16; ks++) {
            int s = ks & 3;
            u32 ahi[4] = { rh[s].x, rh[s].y, rh[s].z, rh[s].w };
            u32 alo[4] = { rl[s].x, rl[s].y, rl[s].z, rl[s].w };
            if (ks < 12) {
                rh[s] = *(const uint4*)(ah + (ks + 4) * 512);
                rl[s] = *(const uint4*)(ah + VERB + (ks + 4) * 512);
            }
            int kg = kq * 16 + ks;
            int p = ks & 1;
            #pragma unroll
            for (int nt = 0; nt < 3; nt++) {
                u32 bw0, bw1, bw2, bw3;   // p0q0, p0q1, p1q0, p1q1
                asm volatile("ld.shared.v4.u32 {%0,%1,%2,%3}, [%4];"
                    : "=r"(bw0), "=r"(bw1), "=r"(bw2), "=r"(bw3)
                    : "r"(sB + (u32)((((kg * 3 + nt) * 32 + l) * 4) * 4)));
                mma_bf16(acc[p][nt], ahi, bw0, bw1);
                mma_bf16(acc[p][nt], ahi, bw2, bw3);
                mma_bf16(acc[p][nt], alo, bw0, bw1);
            }
        }

        // kq 1..3 publish their partials (sum of parity sets)
        if (kq > 0) {
            #pragma unroll
            for (int nt = 0; nt < 3; nt++)
                #pragma unroll
                for (int i = 0; i < 4; i++)
                    s_part[kq - 1][mt][l][nt * 4 + i] = acc[0][nt][i] + acc[1][nt][i];
        }
        __syncthreads();

        // ---- epilogue: kq==0 warps combine + gates + fragment-direct emit ----
        if (kq == 0) {
            float ac[3][4];
            #pragma unroll
            for (int nt = 0; nt < 3; nt++)
                #pragma unroll
                for (int i = 0; i < 4; i++)
                    ac[nt][i] = acc[0][nt][i] + acc[1][nt][i]
                              + s_part[0][mt][l][nt * 4 + i]
                              + s_part[1][mt][l][nt * 4 + i]
                              + s_part[2][mt][l][nt * 4 + i];

            float* hp_out = g_HP + (size_t)(t + 1) * HB;
            unsigned char* ya = g_YA + (size_t)(t + 1) * SLAB;
            u32 whi[2], wlo[2];
            #pragma unroll
            for (int hf = 0; hf < 2; hf++) {
                int b = hf ? b1 : b0;
                float2 er = hf ? ewr1 : ewr0;
                float2 ez = hf ? ewz1 : ewz0;
                float2 en = hf ? ewn1 : ewn0;
                float2 hold = hf ? hold1 : hold0;
                float sr0 = ac[0][hf * 2], sr1 = ac[0][hf * 2 + 1];
                float sz0 = ac[1][hf * 2], sz1 = ac[1][hf * 2 + 1];
                float sn0 = ac[2][hf * 2], sn1 = ac[2][hf * 2 + 1];
                float r0 = 1.0f / (1.0f + __expf(-(er.x + sr0)));
                float r1 = 1.0f / (1.0f + __expf(-(er.y + sr1)));
                float z0 = 1.0f / (1.0f + __expf(-(ez.x + sz0)));
                float z1 = 1.0f / (1.0f + __expf(-(ez.y + sz1)));
                float n0 = tanhf(en.x + r0 * (sn0 + s_bh[jj0]));
                float n1 = tanhf(en.y + r1 * (sn1 + s_bh[jj1]));
                float h0 = (1.0f - z0) * n0 + z0 * hold.x;
                float h1 = (1.0f - z1) * n1 + z1 * hold.y;
                *(float2*)(hp_out + (size_t)b * Hn + ja) = make_float2(h0, h1);
                unsigned short hi0 = bf16r(h0), hi1 = bf16r(h1);
                float f0 = h0 - __bfloat162float(__ushort_as_bfloat16(hi0));
                float f1 = h1 - __bfloat162float(__ushort_as_bfloat16(hi1));
                whi[hf] = (u32)hi0 | ((u32)hi1 << 16);
                wlo[hf] = (u32)bf16r(f0) | ((u32)bf16r(f1) << 16);
            }
            // fragment words: a0/a1 (colbase=0) or a2/a3 (colbase=8) of THIS lane
            u32 base = (u32)(mt * 32768 + ksj * 512 + l * 16 + colbase);
            *(uint2*)(ya + base)        = make_uint2(whi[0], whi[1]);
            *(uint2*)(ya + VERB + base) = make_uint2(wlo[0], wlo[1]);
        }

        // ---- grid barrier: atomic arrive, flag release, flag spin ----
        __syncthreads();
        if (tid == 0) {
            __threadfence();
            unsigned r = atomicAdd(&g_ctr, 1u);
            unsigned target = (unsigned)NBLK * (unsigned)(t + 1);
            if (r == target - 1u) {
                g_go = target;
            }
            while (g_go < target) { }
            __threadfence();
        }
        __syncthreads();
    }
}

// =================== logits = Y @ Wout + bout (FFMA2, reads g_HP [t][b][j]) ===================
__device__ __forceinline__ u64 fma2(u64 a, u64 b, u64 c) {
    u64 d; asm("fma.rn.f32x2 %0, %1, %2, %3;" : "=l"(d) : "l"(a), "l"(b), "l"(c)); return d;
}
__device__ __forceinline__ u64 pack2(float x) {
    u64 d; asm("mov.b64 %0, {%1, %1};" : "=l"(d) : "f"(x)); return d;
}

__global__ __launch_bounds__(256, 1) void out_kernel(const float* __restrict__ Wout,
                                                     const float* __restrict__ bout,
                                                     float* __restrict__ out) {
    __shared__ float sY[32 * Bn];
    __shared__ float sW[32 * 128];
    int t = blockIdx.y;
    int vbase = blockIdx.x * 128;
    int tid = threadIdx.x;
    int bq = tid & 15, vq = tid >> 4;
    int bb = bq * 4, vv0 = vq * 8;
    const float* Yt = g_HP + (size_t)(t + 1) * HB;

    u64 acc2[4][4];
    #pragma unroll
    for (int i = 0; i < 4; i++)
        #pragma unroll
        for (int j = 0; j < 4; j++) acc2[i][j] = 0ull;

    for (int kc = 0; kc < Hn; kc += 32) {
        #pragma unroll
        for (int n = 0; n < 2; n++) {
            int u = tid + n * 256;          // 0..511
            int b = u >> 3, kq = u & 7;     // b 0..63, kq 0..7
            float4 v4 = *(const float4*)(Yt + (size_t)b * Hn + kc + kq * 4);
            sY[(kq * 4 + 0) * Bn + b] = v4.x;
            sY[(kq * 4 + 1) * Bn + b] = v4.y;
            sY[(kq * 4 + 2) * Bn + b] = v4.z;
            sY[(kq * 4 + 3) * Bn + b] = v4.w;
        }
        for (int i = tid; i < 32 * 128 / 4; i += 256) {
            int kk = i >> 5, v4i = (i & 31) * 4;
            ((float4*)sW)[i] = *(const float4*)(Wout + (size_t)(kc + kk) * Vn + vbase + v4i);
        }
        __syncthreads();
        #pragma unroll 4
        for (int kk = 0; kk < 32; kk++) {
            float4 y4 = *(const float4*)(sY + kk * Bn + bb);
            ulonglong2 wA = *(const ulonglong2*)(sW + kk * 128 + vv0);
            ulonglong2 wB = *(const ulonglong2*)(sW + kk * 128 + vv0 + 4);
            u64 wp[4] = {wA.x, wA.y, wB.x, wB.y};
            u64 yy[4] = {pack2(y4.x), pack2(y4.y), pack2(y4.z), pack2(y4.w)};
            #pragma unroll
            for (int i = 0; i < 4; i++)
                #pragma unroll
                for (int j = 0; j < 4; j++)
                    acc2[i][j] = fma2(yy[i], wp[j], acc2[i][j]);
        }
        __syncthreads();
    }

    float4 ba = *(const float4*)(bout + vbase + vv0);
    float4 bbv = *(const float4*)(bout + vbase + vv0 + 4);
    float bs[8] = {ba.x, ba.y, ba.z, ba.w, bbv.x, bbv.y, bbv.z, bbv.w};
    #pragma unroll
    for (int i = 0; i < 4; i++) {
        float vals[8];
        #pragma unroll
        for (int j = 0; j < 4; j++) {
            unsigned lo, hi;
            asm("mov.b64 {%0, %1}, %2;" : "=r"(lo), "=r"(hi) : "l"(acc2[i][j]));
            vals[2 * j] = __uint_as_float(lo);
            vals[2 * j + 1] = __uint_as_float(hi);
        }
        float* po = out + (size_t)(bb + i) * Ln * Vn + (size_t)t * Vn + vbase + vv0;
        float4 o0, o1;
        o0.x = vals[0] + bs[0]; o0.y = vals[1] + bs[1];
        o0.z = vals[2] + bs[2]; o0.w = vals[3] + bs[3];
        o1.x = vals[4] + bs[4]; o1.y = vals[5] + bs[5];
        o1.z = vals[6] + bs[6]; o1.w = vals[7] + bs[7];
        *(float4*)(po + 0) = o0;
        *(float4*)(po + 4) = o1;
    }
}

// =================== launch ===================
extern "C" void kernel_launch(void* const* d_in, const int* in_sizes, int n_in,
                              void* d_out, int out_size) {
    const int*   tokens = (const int*)d_in[0];
    const float* emb    = (const float*)d_in[1];
    const float* Wi     = (const float*)d_in[2];
    const float* Wh     = (const float*)d_in[3];
    const float* bh     = (const float*)d_in[4];
    const float* Wout   = (const float*)d_in[5];
    const float* bout   = (const float*)d_in[6];
    float* out = (float*)d_out;

    cudaFuncSetAttribute(gru_kernel, cudaFuncAttributeMaxDynamicSharedMemorySize, SMEM_DYN);

    reset_kernel<<<64, 256>>>();
    ew_kernel<<<dim3(24, 8), 256>>>(emb, Wi, bh);
    wprep_kernel<<<NBLK, 256>>>(Wh);
    gru_kernel<<<NBLK, 512, SMEM_DYN>>>(tokens, bh);
    out_kernel<<<dim3(2, 256), 256>>>(Wout, bout, out);
}